// round 1
// baseline (speedup 1.0000x reference)
#include <cuda_runtime.h>
#include <math.h>

// Problem constants (fixed shapes from reference setup_inputs)
#define BATCH 256
#define DIM   1024
#define L_IM  37
#define L_S   33
#define LI    36      // image regions after dropping CLS (rows 1..36)
#define LS    30      // sentence words after dropping [:,1:-2] (rows 1..30)
#define MARGIN 0.2f

// Scratch (device globals: allocation-free rule)
__device__ float g_im[BATCH * LI * DIM];     // normalized image regions   [9216, 1024]
__device__ float g_s [BATCH * LS * DIM];     // normalized sentence words  [7680, 1024]
__device__ float g_scores[BATCH * BATCH];    // similarity matrix [256,256]

// ---------------------------------------------------------------------------
// Kernel 1: per-row L2 normalize + slice. One block per OUTPUT row.
// which==0: im_set (Lin=37, Lout=36) -> g_im ; which==1: s_seq (33, 30) -> g_s
// ---------------------------------------------------------------------------
__global__ void norm_kernel(const float* __restrict__ in, int Lin, int Lout, int which)
{
    int ob = blockIdx.x;            // 0 .. BATCH*Lout-1
    int b  = ob / Lout;
    int i  = ob % Lout;             // output row i corresponds to input row i+1
    const float4* src = (const float4*)(in + ((size_t)b * Lin + i + 1) * DIM);
    float4 v = src[threadIdx.x];    // 256 threads * 4 = 1024 elems

    float ss = v.x*v.x + v.y*v.y + v.z*v.z + v.w*v.w;
    #pragma unroll
    for (int o = 16; o > 0; o >>= 1) ss += __shfl_down_sync(0xffffffffu, ss, o);

    __shared__ float warp_s[8];
    __shared__ float inv_s;
    if ((threadIdx.x & 31) == 0) warp_s[threadIdx.x >> 5] = ss;
    __syncthreads();
    if (threadIdx.x == 0) {
        float tot = 0.f;
        #pragma unroll
        for (int q = 0; q < 8; q++) tot += warp_s[q];
        inv_s = 1.0f / fmaxf(sqrtf(tot), 1e-12f);
    }
    __syncthreads();
    float inv = inv_s;
    float* dst = (which ? g_s : g_im) + ((size_t)b * Lout + i) * DIM;
    float4 o4 = make_float4(v.x * inv, v.y * inv, v.z * inv, v.w * inv);
    ((float4*)dst)[threadIdx.x] = o4;
}

// ---------------------------------------------------------------------------
// Kernel 2: fused cross-similarity GEMM + masked max-over-regions +
//           sum-over-words. Block = (1 image b) x (8 sentences = 240 cols).
//   grid = (32 col-tiles, 256 images), 144 threads, thread tile 6x10.
// ---------------------------------------------------------------------------
#define BK   32
#define BN   240
#define NTH  144
#define AS_STRIDE 37     // LI + 1 (odd -> conflict-free transposed stores)
#define BS_STRIDE 241    // BN + 1

__global__ __launch_bounds__(NTH) void score_kernel(const int* __restrict__ im_len,
                                                    const int* __restrict__ s_len)
{
    __shared__ float sm[BK * AS_STRIDE + BK * BS_STRIDE];   // 8896 floats = 35.6 KB
    float* As = sm;                     // [BK][AS_STRIDE]  (k-major, transposed)
    float* Bs = sm + BK * AS_STRIDE;    // [BK][BS_STRIDE]

    const int t  = threadIdx.x;
    const int ty = t / 24;              // 0..5  -> rows  {ty, ty+6, ..., ty+30}
    const int tx = t % 24;              // 0..23 -> cols  {tx, tx+24, ..., tx+216}
    const int b  = blockIdx.y;
    const int n0 = blockIdx.x * BN;

    const float* Ag = g_im + (size_t)b  * LI * DIM;
    const float* Bg = g_s  + (size_t)n0 * DIM;

    float acc[6][10];
    #pragma unroll
    for (int r = 0; r < 6; r++)
        #pragma unroll
        for (int c = 0; c < 10; c++) acc[r][c] = 0.f;

    for (int k0 = 0; k0 < DIM; k0 += BK) {
        // --- load A tile: 36 rows x 32 k = 288 float4, 2 per thread ---
        #pragma unroll
        for (int it = 0; it < 2; ++it) {
            int idx = t + it * NTH;           // < 288
            int row = idx >> 3, kq = idx & 7;
            float4 v = *(const float4*)(Ag + row * DIM + k0 + kq * 4);
            As[(kq*4+0)*AS_STRIDE + row] = v.x;
            As[(kq*4+1)*AS_STRIDE + row] = v.y;
            As[(kq*4+2)*AS_STRIDE + row] = v.z;
            As[(kq*4+3)*AS_STRIDE + row] = v.w;
        }
        // --- load B tile: 240 rows x 32 k = 1920 float4 ---
        #pragma unroll
        for (int it = 0; it < 14; ++it) {
            int idx = t + it * NTH;
            if (idx < 1920) {
                int row = idx >> 3, kq = idx & 7;
                float4 v = *(const float4*)(Bg + row * DIM + k0 + kq * 4);
                Bs[(kq*4+0)*BS_STRIDE + row] = v.x;
                Bs[(kq*4+1)*BS_STRIDE + row] = v.y;
                Bs[(kq*4+2)*BS_STRIDE + row] = v.z;
                Bs[(kq*4+3)*BS_STRIDE + row] = v.w;
            }
        }
        __syncthreads();

        #pragma unroll
        for (int kk = 0; kk < BK; ++kk) {
            float a[6], bb[10];
            #pragma unroll
            for (int r = 0; r < 6; r++)  a[r]  = As[kk*AS_STRIDE + ty + 6*r];
            #pragma unroll
            for (int c = 0; c < 10; c++) bb[c] = Bs[kk*BS_STRIDE + tx + 24*c];
            #pragma unroll
            for (int r = 0; r < 6; r++)
                #pragma unroll
                for (int c = 0; c < 10; c++) acc[r][c] = fmaf(a[r], bb[c], acc[r][c]);
        }
        __syncthreads();
    }

    // ---- epilogue: masked column max over 36 image rows ----
    int iml = im_len[b] - 1;               // valid image rows: i < iml (9..36)
    bool pad = (iml < LI);                 // reference zeros invalid rows -> 0 joins max

    float cm[10];
    #pragma unroll
    for (int c = 0; c < 10; c++) {
        float m = -1e30f;
        #pragma unroll
        for (int r = 0; r < 6; r++) {
            int row = ty + 6*r;
            if (row < iml) m = fmaxf(m, acc[r][c]);
        }
        cm[c] = m;
    }
    __syncthreads();                        // smem tiles dead; reuse as scratch
    float* red    = sm;                     // [6][240]
    float* colmax = sm + 6 * BN;            // [240]
    #pragma unroll
    for (int c = 0; c < 10; c++) red[ty * BN + tx + 24*c] = cm[c];
    __syncthreads();
    if (ty == 0) {
        #pragma unroll
        for (int c = 0; c < 10; c++) {
            int col = tx + 24*c;
            float m = red[col];
            #pragma unroll
            for (int q = 1; q < 6; q++) m = fmaxf(m, red[q * BN + col]);
            if (pad) m = fmaxf(m, 0.f);
            colmax[col] = m;
        }
    }
    __syncthreads();

    // ---- sum over valid words per sentence; one writer per (b, c) ----
    if (t < 8) {
        int cs = blockIdx.x * 8 + t;
        int sl = s_len[cs] - 3;
        if (sl > LS) sl = LS;
        if (sl < 0)  sl = 0;
        float sum = 0.f;
        for (int j = 0; j < sl; j++) sum += colmax[t * LS + j];
        g_scores[b * BATCH + cs] = sum;
    }
}

// ---------------------------------------------------------------------------
// Kernel 3: contrastive loss over scores [256,256] (single block)
// ---------------------------------------------------------------------------
__global__ void loss_kernel(float* __restrict__ out)
{
    __shared__ float diag[BATCH];
    __shared__ float red[BATCH];
    int t = threadIdx.x;
    diag[t] = g_scores[t * BATCH + t];
    __syncthreads();
    float db = diag[t];
    float rm = 0.f;   // max over cost_s row t   (diag zeroed; relu floors at 0)
    float cm = 0.f;   // max over cost_im column t
    for (int c = 0; c < BATCH; c++) {
        if (c != t) {
            rm = fmaxf(rm, MARGIN + g_scores[t * BATCH + c] - db);
            cm = fmaxf(cm, MARGIN + g_scores[c * BATCH + t] - db);
        }
    }
    red[t] = rm + cm;
    __syncthreads();
    #pragma unroll
    for (int o = 128; o > 0; o >>= 1) {
        if (t < o) red[t] += red[t + o];
        __syncthreads();
    }
    if (t == 0) out[0] = red[0];
}

// ---------------------------------------------------------------------------
extern "C" void kernel_launch(void* const* d_in, const int* in_sizes, int n_in,
                              void* d_out, int out_size)
{
    const float* im_set = (const float*)d_in[0];   // [256,37,1024] f32
    const float* s_seq  = (const float*)d_in[1];   // [256,33,1024] f32
    const int*   im_len = (const int*)d_in[2];     // [256] i32
    const int*   s_len  = (const int*)d_in[3];     // [256] i32
    float* out = (float*)d_out;

    norm_kernel<<<BATCH * LI, 256>>>(im_set, L_IM, LI, 0);
    norm_kernel<<<BATCH * LS, 256>>>(s_seq,  L_S,  LS, 1);

    dim3 grid(BATCH / 8, BATCH);   // (32 col-tiles of 8 sentences, 256 images)
    score_kernel<<<grid, NTH>>>(im_len, s_len);

    loss_kernel<<<1, BATCH>>>(out);
}

// round 3
// speedup vs baseline: 7.6983x; 7.6983x over previous
#include <cuda_runtime.h>
#include <cuda_fp16.h>
#include <math.h>
#include <stdint.h>

// Problem constants
#define BATCH 256
#define DIM   1024
#define L_IM  37
#define L_S   33
#define LI    36
#define LS    30
#define MARGIN 0.2f

#define MROWS  (BATCH*LI)     // 9216
#define NCOLS  (BATCH*LS)     // 7680

// ---- device scratch (allocation-free rule) ----
__device__ __half g_A[(size_t)MROWS * DIM];          // fp16 normalized images   18.9 MB
__device__ __half g_B[(size_t)NCOLS * DIM];          // fp16 normalized words    15.7 MB
__device__ float  g_align[(size_t)MROWS * NCOLS];    // 283 MB
__device__ float  g_scores[BATCH * BATCH];
__device__ float  g_red[BATCH];

__device__ __forceinline__ uint32_t s2u(const void* p) {
    return (uint32_t)__cvta_generic_to_shared(p);
}

// ============================================================================
// Kernel 1: L2-normalize + slice + fp16 convert. One block per output row.
// ============================================================================
__global__ void norm_kernel(const float* __restrict__ in, int Lin, int Lout, int which)
{
    int ob = blockIdx.x;
    int b  = ob / Lout;
    int i  = ob % Lout;
    const float4* src = (const float4*)(in + ((size_t)b * Lin + i + 1) * DIM);
    float4 v = src[threadIdx.x];

    float ss = v.x*v.x + v.y*v.y + v.z*v.z + v.w*v.w;
    #pragma unroll
    for (int o = 16; o > 0; o >>= 1) ss += __shfl_down_sync(0xffffffffu, ss, o);

    __shared__ float warp_s[8];
    __shared__ float inv_s;
    if ((threadIdx.x & 31) == 0) warp_s[threadIdx.x >> 5] = ss;
    __syncthreads();
    if (threadIdx.x == 0) {
        float tot = 0.f;
        #pragma unroll
        for (int q = 0; q < 8; q++) tot += warp_s[q];
        inv_s = 1.0f / fmaxf(sqrtf(tot), 1e-12f);
    }
    __syncthreads();
    float inv = inv_s;

    __half2 h01 = __floats2half2_rn(v.x * inv, v.y * inv);
    __half2 h23 = __floats2half2_rn(v.z * inv, v.w * inv);
    __half* dst = (which ? g_B : g_A) + (size_t)ob * DIM + 4 * threadIdx.x;
    *(__half2*)(dst)     = h01;
    *(__half2*)(dst + 2) = h23;
}

// ============================================================================
// Kernel 2: fp16 mma.sync GEMM  align = A * B^T  (fp32 accumulate)
//   CTA 128x128x32, 256 threads, 8 warps of 64x32, 4-stage cp.async pipeline.
// ============================================================================
#define BM 128
#define BN 128
#define BKH 32                      // K halfs per stage
#define STAGES 4
#define ROWB 80                     // padded smem row bytes (32 halfs + 8 pad)
#define STAGE_BYTES ((BM + BN) * ROWB)   // 20480
#define KTILES (DIM / BKH)          // 32

__device__ __forceinline__ void cp16(uint32_t dst, const void* src) {
    asm volatile("cp.async.cg.shared.global [%0], [%1], 16;" :: "r"(dst), "l"(src));
}

__device__ __forceinline__ void load_stage(char* dsm, int slot, int m0, int n0, int kc, int t)
{
    char* As = dsm + slot * STAGE_BYTES;
    char* Bs = As + BM * ROWB;
    const __half* Agp = g_A + (size_t)m0 * DIM + kc * BKH;
    const __half* Bgp = g_B + (size_t)n0 * DIM + kc * BKH;
    #pragma unroll
    for (int i = 0; i < 2; i++) {
        int idx = t + i * 256;             // 0..511
        int row = idx >> 2, seg = idx & 3;
        cp16(s2u(As + row * ROWB + seg * 16), Agp + (size_t)row * DIM + seg * 8);
    }
    #pragma unroll
    for (int i = 0; i < 2; i++) {
        int idx = t + i * 256;
        int row = idx >> 2, seg = idx & 3;
        cp16(s2u(Bs + row * ROWB + seg * 16), Bgp + (size_t)row * DIM + seg * 8);
    }
}

__global__ __launch_bounds__(256, 2) void gemm_kernel()
{
    extern __shared__ __align__(128) char dsm[];
    const int t   = threadIdx.x;
    const int wid = t >> 5, lid = t & 31;
    const int warp_m = (wid & 1) * 64;
    const int warp_n = (wid >> 1) * 32;
    const int m0 = blockIdx.y * BM;
    const int n0 = blockIdx.x * BN;

    float acc[4][4][4];
    #pragma unroll
    for (int mf = 0; mf < 4; mf++)
        #pragma unroll
        for (int nf = 0; nf < 4; nf++)
            #pragma unroll
            for (int q = 0; q < 4; q++) acc[mf][nf][q] = 0.f;

    // prologue: fill stages 0..2
    #pragma unroll
    for (int s = 0; s < STAGES - 1; s++) {
        load_stage(dsm, s, m0, n0, s, t);
        asm volatile("cp.async.commit_group;");
    }

    for (int j = 0; j < KTILES; j++) {
        // wait for stage j (pending = stages in flight beyond j)
        if (j < KTILES - 2)       asm volatile("cp.async.wait_group 2;");
        else if (j == KTILES - 2) asm volatile("cp.async.wait_group 1;");
        else                      asm volatile("cp.async.wait_group 0;");
        __syncthreads();

        int jl = j + STAGES - 1;
        if (jl < KTILES) {
            load_stage(dsm, jl & 3, m0, n0, jl, t);
            asm volatile("cp.async.commit_group;");
        }

        char* As = dsm + (j & 3) * STAGE_BYTES;
        char* Bs = As + BM * ROWB;
        const uint32_t AsU = s2u(As);

        #pragma unroll
        for (int ks = 0; ks < 2; ks++) {
            uint32_t a[4][4];
            #pragma unroll
            for (int mf = 0; mf < 4; mf++) {
                uint32_t addr = AsU + (warp_m + mf * 16 + (lid & 15)) * ROWB
                                    + ((lid >> 4) * 8 + ks * 16) * 2;
                asm volatile("ldmatrix.sync.aligned.m8n8.x4.shared.b16 {%0,%1,%2,%3}, [%4];"
                    : "=r"(a[mf][0]), "=r"(a[mf][1]), "=r"(a[mf][2]), "=r"(a[mf][3])
                    : "r"(addr));
            }
            #pragma unroll
            for (int nf = 0; nf < 4; nf++) {
                int n = warp_n + nf * 8 + (lid >> 2);
                uint32_t b0 = *(const uint32_t*)(Bs + n * ROWB + (ks * 16 + (lid & 3) * 2) * 2);
                uint32_t b1 = *(const uint32_t*)(Bs + n * ROWB + (ks * 16 + 8 + (lid & 3) * 2) * 2);
                #pragma unroll
                for (int mf = 0; mf < 4; mf++) {
                    asm volatile(
                        "mma.sync.aligned.m16n8k16.row.col.f32.f16.f16.f32 "
                        "{%0,%1,%2,%3}, {%4,%5,%6,%7}, {%8,%9}, {%0,%1,%2,%3};"
                        : "+f"(acc[mf][nf][0]), "+f"(acc[mf][nf][1]),
                          "+f"(acc[mf][nf][2]), "+f"(acc[mf][nf][3])
                        : "r"(a[mf][0]), "r"(a[mf][1]), "r"(a[mf][2]), "r"(a[mf][3]),
                          "r"(b0), "r"(b1));
                }
            }
        }
    }

    // epilogue: direct streaming stores
    const int rbase = m0 + warp_m + (lid >> 2);
    const int cbase = n0 + warp_n + (lid & 3) * 2;
    #pragma unroll
    for (int mf = 0; mf < 4; mf++) {
        #pragma unroll
        for (int nf = 0; nf < 4; nf++) {
            int r = rbase + mf * 16;
            int c = cbase + nf * 8;
            float2 v0 = make_float2(acc[mf][nf][0], acc[mf][nf][1]);
            float2 v1 = make_float2(acc[mf][nf][2], acc[mf][nf][3]);
            __stcs((float2*)(g_align + (size_t)r * NCOLS + c), v0);
            __stcs((float2*)(g_align + (size_t)(r + 8) * NCOLS + c), v1);
        }
    }
}

// ============================================================================
// Kernel 3: masked max-over-regions + sum-over-words. One warp per (b,c).
// ============================================================================
__global__ void reduce_kernel(const int* __restrict__ im_len, const int* __restrict__ s_len)
{
    int wid = threadIdx.x >> 5, lid = threadIdx.x & 31;
    int p = blockIdx.x * 8 + wid;
    int b = p >> 8, c = p & 255;
    int iml = im_len[b] - 1;
    int sl  = s_len[c] - 3;
    if (sl > LS) sl = LS;
    if (sl < 0)  sl = 0;

    const float* base = g_align + ((size_t)b * LI) * NCOLS + c * LS;
    float mx = -1e30f;
    if (lid < LS) {
        for (int i = 0; i < iml; i++)
            mx = fmaxf(mx, __ldcs(base + (size_t)i * NCOLS + lid));
        if (iml < LI) mx = fmaxf(mx, 0.f);
    }
    float v = (lid < sl) ? mx : 0.f;
    #pragma unroll
    for (int o = 16; o > 0; o >>= 1) v += __shfl_down_sync(0xffffffffu, v, o);
    if (lid == 0) g_scores[b * BATCH + c] = v;
}

// ============================================================================
// Kernel 4/5: contrastive loss
// ============================================================================
__global__ void loss1_kernel()
{
    int b = blockIdx.x, t = threadIdx.x;
    __shared__ float sd;
    __shared__ float w1[8], w2[8];
    if (t == 0) sd = g_scores[b * BATCH + b];
    __syncthreads();
    float d = sd;
    float v1 = 0.f, v2 = 0.f;
    if (t != b) {
        v1 = fmaxf(0.f, MARGIN + g_scores[b * BATCH + t] - d);
        v2 = fmaxf(0.f, MARGIN + g_scores[t * BATCH + b] - d);
    }
    #pragma unroll
    for (int o = 16; o > 0; o >>= 1) {
        v1 = fmaxf(v1, __shfl_down_sync(0xffffffffu, v1, o));
        v2 = fmaxf(v2, __shfl_down_sync(0xffffffffu, v2, o));
    }
    if ((t & 31) == 0) { w1[t >> 5] = v1; w2[t >> 5] = v2; }
    __syncthreads();
    if (t == 0) {
        float m1 = w1[0], m2 = w2[0];
        #pragma unroll
        for (int q = 1; q < 8; q++) { m1 = fmaxf(m1, w1[q]); m2 = fmaxf(m2, w2[q]); }
        g_red[b] = m1 + m2;
    }
}
__global__ void loss2_kernel(float* __restrict__ out)
{
    __shared__ float sm[BATCH];
    int t = threadIdx.x;
    sm[t] = g_red[t];
    __syncthreads();
    #pragma unroll
    for (int o = 128; o > 0; o >>= 1) {
        if (t < o) sm[t] += sm[t + o];
        __syncthreads();
    }
    if (t == 0) out[0] = sm[0];
}

// ============================================================================
extern "C" void kernel_launch(void* const* d_in, const int* in_sizes, int n_in,
                              void* d_out, int out_size)
{
    const float* im_set = (const float*)d_in[0];
    const float* s_seq  = (const float*)d_in[1];
    const int*   im_len = (const int*)d_in[2];
    const int*   s_len  = (const int*)d_in[3];
    float* out = (float*)d_out;

    cudaFuncSetAttribute(gemm_kernel, cudaFuncAttributeMaxDynamicSharedMemorySize,
                         STAGES * STAGE_BYTES);

    norm_kernel<<<BATCH * LI, 256>>>(im_set, L_IM, LI, 0);
    norm_kernel<<<BATCH * LS, 256>>>(s_seq,  L_S,  LS, 1);

    dim3 grid(NCOLS / BN, MROWS / BM);   // (60, 72)
    gemm_kernel<<<grid, 256, STAGES * STAGE_BYTES>>>();

    reduce_kernel<<<BATCH * BATCH / 8, 256>>>(im_len, s_len);

    loss1_kernel<<<BATCH, 256>>>();
    loss2_kernel<<<1, BATCH>>>(out);
}

// round 4
// speedup vs baseline: 9.4291x; 1.2248x over previous
#include <cuda_runtime.h>
#include <cuda_fp16.h>
#include <math.h>
#include <stdint.h>

// Problem constants
#define BATCH 256
#define DIM   1024
#define L_IM  37
#define L_S   33
#define LI    36
#define LS    30
#define MARGIN 0.2f

#define MROWS  (BATCH*LI)     // 9216
#define NCOLS  (BATCH*LS)     // 7680

// ---- device scratch (allocation-free rule) ----
__device__ __half g_A[(size_t)MROWS * DIM];          // fp16 normalized images   18.9 MB
__device__ __half g_B[(size_t)NCOLS * DIM];          // fp16 normalized words    15.7 MB
__device__ float  g_colmax[(size_t)BATCH * NCOLS];   // masked max over regions  7.9 MB
__device__ float  g_scores[BATCH * BATCH];
__device__ float  g_red[BATCH];

__device__ __forceinline__ uint32_t s2u(const void* p) {
    return (uint32_t)__cvta_generic_to_shared(p);
}

// ============================================================================
// Kernel 1: L2-normalize + slice + fp16 convert. One block per output row.
// ============================================================================
__global__ void norm_kernel(const float* __restrict__ in, int Lin, int Lout, int which)
{
    int ob = blockIdx.x;
    int b  = ob / Lout;
    int i  = ob % Lout;
    const float4* src = (const float4*)(in + ((size_t)b * Lin + i + 1) * DIM);
    float4 v = src[threadIdx.x];

    float ss = v.x*v.x + v.y*v.y + v.z*v.z + v.w*v.w;
    #pragma unroll
    for (int o = 16; o > 0; o >>= 1) ss += __shfl_down_sync(0xffffffffu, ss, o);

    __shared__ float warp_s[8];
    __shared__ float inv_s;
    if ((threadIdx.x & 31) == 0) warp_s[threadIdx.x >> 5] = ss;
    __syncthreads();
    if (threadIdx.x == 0) {
        float tot = 0.f;
        #pragma unroll
        for (int q = 0; q < 8; q++) tot += warp_s[q];
        inv_s = 1.0f / fmaxf(sqrtf(tot), 1e-12f);
    }
    __syncthreads();
    float inv = inv_s;

    __half2 h01 = __floats2half2_rn(v.x * inv, v.y * inv);
    __half2 h23 = __floats2half2_rn(v.z * inv, v.w * inv);
    __half* dst = (which ? g_B : g_A) + (size_t)ob * DIM + 4 * threadIdx.x;
    *(__half2*)(dst)     = h01;
    *(__half2*)(dst + 2) = h23;
}

// ============================================================================
// Kernel 2: fp16 mma.sync GEMM with FUSED masked max-over-regions epilogue.
//   CTA 144x128x32 (144 rows = exactly 4 images), 192 threads,
//   6 warps of 48x64, 4-stage cp.async pipeline, fp32 accum.
//   Epilogue: accs -> smem tile -> per-(image,col) masked max -> g_colmax.
// ============================================================================
#define BM 144
#define BN 128
#define BKH 32                      // K halfs per stage
#define STAGES 4
#define ROWB 80                     // padded smem row bytes (32 halfs + 8 pad)
#define STAGE_BYTES ((BM + BN) * ROWB)   // 21760
#define KTILES (DIM / BKH)          // 32
#define NTH 192
#define ESTR 132                    // epilogue fp32 tile row stride (floats)

__device__ __forceinline__ void cp16(uint32_t dst, const void* src) {
    asm volatile("cp.async.cg.shared.global [%0], [%1], 16;" :: "r"(dst), "l"(src));
}

__device__ __forceinline__ void load_stage(char* dsm, int slot, int m0, int n0, int kc, int t)
{
    char* As = dsm + slot * STAGE_BYTES;
    char* Bs = As + BM * ROWB;
    const __half* Agp = g_A + (size_t)m0 * DIM + kc * BKH;
    const __half* Bgp = g_B + (size_t)n0 * DIM + kc * BKH;
    #pragma unroll
    for (int i = 0; i < 3; i++) {                 // 576 = 3 * 192 A-vectors
        int idx = t + i * NTH;
        int row = idx >> 2, seg = idx & 3;
        cp16(s2u(As + row * ROWB + seg * 16), Agp + (size_t)row * DIM + seg * 8);
    }
    #pragma unroll
    for (int i = 0; i < 3; i++) {                 // 512 B-vectors (last iter partial)
        int idx = t + i * NTH;
        if (idx < 512) {
            int row = idx >> 2, seg = idx & 3;
            cp16(s2u(Bs + row * ROWB + seg * 16), Bgp + (size_t)row * DIM + seg * 8);
        }
    }
}

__global__ __launch_bounds__(NTH, 2) void gemm_kernel(const int* __restrict__ im_len)
{
    extern __shared__ __align__(128) char dsm[];
    const int t   = threadIdx.x;
    const int wid = t >> 5, lid = t & 31;
    const int warp_m = (wid % 3) * 48;
    const int warp_n = (wid / 3) * 64;
    const int m0 = blockIdx.y * BM;
    const int n0 = blockIdx.x * BN;

    float acc[3][8][4];
    #pragma unroll
    for (int mf = 0; mf < 3; mf++)
        #pragma unroll
        for (int nf = 0; nf < 8; nf++)
            #pragma unroll
            for (int q = 0; q < 4; q++) acc[mf][nf][q] = 0.f;

    // prologue: fill stages 0..2
    #pragma unroll
    for (int s = 0; s < STAGES - 1; s++) {
        load_stage(dsm, s, m0, n0, s, t);
        asm volatile("cp.async.commit_group;");
    }

    for (int j = 0; j < KTILES; j++) {
        if (j < KTILES - 2)       asm volatile("cp.async.wait_group 2;");
        else if (j == KTILES - 2) asm volatile("cp.async.wait_group 1;");
        else                      asm volatile("cp.async.wait_group 0;");
        __syncthreads();

        int jl = j + STAGES - 1;
        if (jl < KTILES) {
            load_stage(dsm, jl & 3, m0, n0, jl, t);
            asm volatile("cp.async.commit_group;");
        }

        char* As = dsm + (j & 3) * STAGE_BYTES;
        char* Bs = As + BM * ROWB;
        const uint32_t AsU = s2u(As);

        #pragma unroll
        for (int ks = 0; ks < 2; ks++) {
            uint32_t a[3][4];
            #pragma unroll
            for (int mf = 0; mf < 3; mf++) {
                uint32_t addr = AsU + (warp_m + mf * 16 + (lid & 15)) * ROWB
                                    + ((lid >> 4) * 8 + ks * 16) * 2;
                asm volatile("ldmatrix.sync.aligned.m8n8.x4.shared.b16 {%0,%1,%2,%3}, [%4];"
                    : "=r"(a[mf][0]), "=r"(a[mf][1]), "=r"(a[mf][2]), "=r"(a[mf][3])
                    : "r"(addr));
            }
            #pragma unroll
            for (int nf = 0; nf < 8; nf++) {
                int n = warp_n + nf * 8 + (lid >> 2);
                uint32_t b0 = *(const uint32_t*)(Bs + n * ROWB + (ks * 16 + (lid & 3) * 2) * 2);
                uint32_t b1 = *(const uint32_t*)(Bs + n * ROWB + (ks * 16 + 8 + (lid & 3) * 2) * 2);
                #pragma unroll
                for (int mf = 0; mf < 3; mf++) {
                    asm volatile(
                        "mma.sync.aligned.m16n8k16.row.col.f32.f16.f16.f32 "
                        "{%0,%1,%2,%3}, {%4,%5,%6,%7}, {%8,%9}, {%0,%1,%2,%3};"
                        : "+f"(acc[mf][nf][0]), "+f"(acc[mf][nf][1]),
                          "+f"(acc[mf][nf][2]), "+f"(acc[mf][nf][3])
                        : "r"(a[mf][0]), "r"(a[mf][1]), "r"(a[mf][2]), "r"(a[mf][3]),
                          "r"(b0), "r"(b1));
                }
            }
        }
    }

    // ---- fused epilogue: accs -> smem fp32 tile [144][128] (stride ESTR) ----
    __syncthreads();                       // all mainloop smem reads complete
    float* etile = (float*)dsm;            // 144*132*4 = 76032 B <= smem budget
    const int r0 = warp_m + (lid >> 2);
    const int c0 = warp_n + (lid & 3) * 2;
    #pragma unroll
    for (int mf = 0; mf < 3; mf++) {
        #pragma unroll
        for (int nf = 0; nf < 8; nf++) {
            int r = r0 + mf * 16;
            int c = c0 + nf * 8;
            etile[r * ESTR + c]           = acc[mf][nf][0];
            etile[r * ESTR + c + 1]       = acc[mf][nf][1];
            etile[(r + 8) * ESTR + c]     = acc[mf][nf][2];
            etile[(r + 8) * ESTR + c + 1] = acc[mf][nf][3];
        }
    }
    __syncthreads();

    // masked column max per (image, col): 4 images x 128 cols = 512 outputs
    const int bimg0 = blockIdx.y * 4;
    for (int idx = t; idx < 512; idx += NTH) {
        int img = idx >> 7, col = idx & 127;
        int iml = im_len[bimg0 + img] - 1;           // valid rows (9..36)
        const float* colp = etile + img * 36 * ESTR + col;
        float m = -1e30f;
        for (int r = 0; r < iml; r++) m = fmaxf(m, colp[r * ESTR]);
        if (iml < LI) m = fmaxf(m, 0.f);             // reference zeros padded rows
        g_colmax[(size_t)(bimg0 + img) * NCOLS + n0 + col] = m;
    }
}

// ============================================================================
// Kernel 3: scores[b][c] = sum_{j < sl} colmax[b][c*30+j]. One warp per (b,c).
// ============================================================================
__global__ void score_kernel(const int* __restrict__ s_len)
{
    int wid = threadIdx.x >> 5, lid = threadIdx.x & 31;
    int p = blockIdx.x * 8 + wid;          // 0..65535
    int b = p >> 8, c = p & 255;
    int sl = s_len[c] - 3;
    if (sl > LS) sl = LS;
    if (sl < 0)  sl = 0;
    float v = 0.f;
    if (lid < sl) v = g_colmax[(size_t)b * NCOLS + c * LS + lid];
    #pragma unroll
    for (int o = 16; o > 0; o >>= 1) v += __shfl_down_sync(0xffffffffu, v, o);
    if (lid == 0) g_scores[b * BATCH + c] = v;
}

// ============================================================================
// Kernel 4/5: contrastive loss
// ============================================================================
__global__ void loss1_kernel()
{
    int b = blockIdx.x, t = threadIdx.x;
    __shared__ float sd;
    __shared__ float w1[8], w2[8];
    if (t == 0) sd = g_scores[b * BATCH + b];
    __syncthreads();
    float d = sd;
    float v1 = 0.f, v2 = 0.f;
    if (t != b) {
        v1 = fmaxf(0.f, MARGIN + g_scores[b * BATCH + t] - d);
        v2 = fmaxf(0.f, MARGIN + g_scores[t * BATCH + b] - d);
    }
    #pragma unroll
    for (int o = 16; o > 0; o >>= 1) {
        v1 = fmaxf(v1, __shfl_down_sync(0xffffffffu, v1, o));
        v2 = fmaxf(v2, __shfl_down_sync(0xffffffffu, v2, o));
    }
    if ((t & 31) == 0) { w1[t >> 5] = v1; w2[t >> 5] = v2; }
    __syncthreads();
    if (t == 0) {
        float m1 = w1[0], m2 = w2[0];
        #pragma unroll
        for (int q = 1; q < 8; q++) { m1 = fmaxf(m1, w1[q]); m2 = fmaxf(m2, w2[q]); }
        g_red[b] = m1 + m2;
    }
}
__global__ void loss2_kernel(float* __restrict__ out)
{
    __shared__ float sm[BATCH];
    int t = threadIdx.x;
    sm[t] = g_red[t];
    __syncthreads();
    #pragma unroll
    for (int o = 128; o > 0; o >>= 1) {
        if (t < o) sm[t] += sm[t + o];
        __syncthreads();
    }
    if (t == 0) out[0] = sm[0];
}

// ============================================================================
extern "C" void kernel_launch(void* const* d_in, const int* in_sizes, int n_in,
                              void* d_out, int out_size)
{
    const float* im_set = (const float*)d_in[0];
    const float* s_seq  = (const float*)d_in[1];
    const int*   im_len = (const int*)d_in[2];
    const int*   s_len  = (const int*)d_in[3];
    float* out = (float*)d_out;

    cudaFuncSetAttribute(gemm_kernel, cudaFuncAttributeMaxDynamicSharedMemorySize,
                         STAGES * STAGE_BYTES);

    norm_kernel<<<BATCH * LI, 256>>>(im_set, L_IM, LI, 0);
    norm_kernel<<<BATCH * LS, 256>>>(s_seq,  L_S,  LS, 1);

    dim3 grid(NCOLS / BN, MROWS / BM);   // (60, 64)
    gemm_kernel<<<grid, NTH, STAGES * STAGE_BYTES>>>(im_len);

    score_kernel<<<BATCH * BATCH / 8, 256>>>(s_len);

    loss1_kernel<<<BATCH, 256>>>();
    loss2_kernel<<<1, BATCH>>>(out);
}